// round 7
// baseline (speedup 1.0000x reference)
#include <cuda_runtime.h>
#include <cstddef>

#define HH 51
#define GG 204
#define BT 16
#define NTH 416      // 13 warps: 12.75 warps' worth of (gate, k-half) pairs
#define TT 512
#define BB 2048
#define AGP 20       // padded ag row stride
#define TCH 64
#define KQ 26        // k-rows per half (second half uses zero-pad row 51)

typedef unsigned long long u64;

__device__ __forceinline__ u64 pack2(float lo, float hi) {
    u64 r; asm("mov.b64 %0, {%1,%2};" : "=l"(r) : "f"(lo), "f"(hi)); return r;
}
__device__ __forceinline__ void unpack2(u64 v, float& lo, float& hi) {
    asm("mov.b64 {%0,%1}, %2;" : "=f"(lo), "=f"(hi) : "l"(v));
}
__device__ __forceinline__ u64 fma2(u64 a, u64 b, u64 c) {
    u64 d; asm("fma.rn.f32x2 %0, %1, %2, %3;" : "=l"(d) : "l"(a), "l"(b), "l"(c)); return d;
}
__device__ __forceinline__ float actf(float v, float c, float a, float d) {
    float e; asm("ex2.approx.ftz.f32 %0, %1;" : "=f"(e) : "f"(v * c));
    float r; asm("rcp.approx.ftz.f32 %0, %1;" : "=f"(r) : "f"(1.f + e));
    return fmaf(a, r, d);
}
#define C_SIG (-1.442695041f)
#define C_TNH ( 2.885390082f)
__device__ __forceinline__ float tanh_c(float v) { return actf(v, C_TNH, -2.f, 1.f); }

__global__ void __launch_bounds__(NTH, 1) lstm2_ksplit_kernel(
    const float* __restrict__ x,
    const float* __restrict__ Wih1, const float* __restrict__ bih1,
    const float* __restrict__ Whh1, const float* __restrict__ bhh1,
    const float* __restrict__ Wih2, const float* __restrict__ bih2,
    const float* __restrict__ Whh2, const float* __restrict__ bhh2,
    const float* __restrict__ fcwg, const float* __restrict__ fcbg,
    float* __restrict__ out)
{
    __shared__ __align__(16) float h1[52*BT];     // rows 0..50 live, row 51 = 0 pad
    __shared__ __align__(16) float h2[52*BT];
    __shared__ __align__(16) float ag[GG*AGP];    // [gate][20pad]
    __shared__ __align__(16) float xs2[TCH*BT];   // [tc][b]
    __shared__ float sfcw[HH];

    const int tid  = threadIdx.x;
    const int b0   = blockIdx.x * BT;
    const int warp = tid >> 5, lane = tid & 31;
    const int khalf = lane >> 4;                  // 0: k 0..25, 1: k 26..51(pad)
    const int g = warp * 16 + (lane & 15);
    const bool valid = (g < GG);
    const int gs  = valid ? g : (GG - 1);
    const int cls = gs / HH;                      // 0:i 1:f 2:g 3:o
    const int koff = khalf * KQ;

    // ---- weights into registers (one-time), zero-padded past k=50 ----
    float W1r[KQ], Wi2r[KQ], Wh2r[KQ];
#pragma unroll
    for (int j = 0; j < KQ; ++j) {
        int k = koff + j;
        bool kv = (k < HH);
        W1r[j]  = kv ? Whh1[gs*HH + k] : 0.f;
        Wi2r[j] = kv ? Wih2[gs*HH + k] : 0.f;
        Wh2r[j] = kv ? Whh2[gs*HH + k] : 0.f;
    }
    const float b1 = bih1[gs] + bhh1[gs];
    const float b2 = bih2[gs] + bhh2[gs];
    const float w1x = Wih1[gs];
    const u64 b1d  = pack2(b1, b1);
    const u64 b2d  = pack2(b2, b2);
    const u64 wi1d = pack2(w1x, w1x);
    const u64 zero = 0ull;

    const float c0 = (cls == 2) ? C_TNH : C_SIG;
    const float a0 = (cls == 2) ? -2.f  : 1.f;
    const float d0 = (cls == 2) ?  1.f  : 0.f;

    for (int i = tid; i < 52*BT; i += NTH) { h1[i] = 0.f; h2[i] = 0.f; }
    if (tid < HH) sfcw[tid] = fcwg[tid];
    const float fcb = fcbg[0];

    // phase B/D mapping: 816 items over 416 threads -> 2 each
    const int i0 = tid, i1 = tid + NTH;
    const bool v1 = (i1 < HH*BT);
    float c1s[2] = {0.f, 0.f}, c2s[2] = {0.f, 0.f};

    const u64* h1p = (const u64*)&h1[koff << 4];  // my k-half base (8 u64 per row)
    const u64* h2p = (const u64*)&h2[koff << 4];
    const int agb = gs * AGP + khalf * 8;         // my 8-batch slot

    __syncthreads();

    for (int t = 0; t < TT; ++t) {
        const int tc = t & (TCH - 1);
        if (tc == 0) {
            for (int i = tid; i < BT*TCH; i += NTH) {
                int b = i >> 6, u = i & 63;
                xs2[(u << 4) + b] = x[(size_t)(b0 + b) * TT + t + u];
            }
            __syncthreads();
        }

        // ================= Phase A: cell-1 gates (k-half partial) ==========
        u64 acc[8];
        if (khalf == 0) {
            const ulonglong2* xr = (const ulonglong2*)&xs2[tc << 4];
            ulonglong2 x01 = xr[0], x23 = xr[1], x45 = xr[2], x67 = xr[3];
            acc[0] = fma2(wi1d, x01.x, b1d);
            acc[1] = fma2(wi1d, x01.y, b1d);
            acc[2] = fma2(wi1d, x23.x, b1d);
            acc[3] = fma2(wi1d, x23.y, b1d);
            acc[4] = fma2(wi1d, x45.x, b1d);
            acc[5] = fma2(wi1d, x45.y, b1d);
            acc[6] = fma2(wi1d, x67.x, b1d);
            acc[7] = fma2(wi1d, x67.y, b1d);
        } else {
#pragma unroll
            for (int i = 0; i < 8; ++i) acc[i] = zero;
        }
#pragma unroll
        for (int j = 0; j < KQ; ++j) {
            u64 wd = pack2(W1r[j], W1r[j]);
            const ulonglong2* hr = (const ulonglong2*)(h1p + (j << 3));
            ulonglong2 p0 = hr[0], p1 = hr[1], p2 = hr[2], p3 = hr[3];
            acc[0] = fma2(wd, p0.x, acc[0]);
            acc[1] = fma2(wd, p0.y, acc[1]);
            acc[2] = fma2(wd, p1.x, acc[2]);
            acc[3] = fma2(wd, p1.y, acc[3]);
            acc[4] = fma2(wd, p2.x, acc[4]);
            acc[5] = fma2(wd, p2.y, acc[5]);
            acc[6] = fma2(wd, p3.x, acc[6]);
            acc[7] = fma2(wd, p3.y, acc[7]);
        }
        {
            float r[16];
#pragma unroll
            for (int i = 0; i < 8; ++i) unpack2(acc[i], r[2*i], r[2*i+1]);
#pragma unroll
            for (int i = 0; i < 16; ++i)
                r[i] += __shfl_xor_sync(0xFFFFFFFFu, r[i], 16);
            const int off = khalf * 8;
            float s0 = actf(r[off+0], c0, a0, d0);
            float s1 = actf(r[off+1], c0, a0, d0);
            float s2 = actf(r[off+2], c0, a0, d0);
            float s3 = actf(r[off+3], c0, a0, d0);
            float s4 = actf(r[off+4], c0, a0, d0);
            float s5 = actf(r[off+5], c0, a0, d0);
            float s6 = actf(r[off+6], c0, a0, d0);
            float s7 = actf(r[off+7], c0, a0, d0);
            if (valid) {
                *(float4*)&ag[agb]     = make_float4(s0, s1, s2, s3);
                *(float4*)&ag[agb + 4] = make_float4(s4, s5, s6, s7);
            }
        }
        __syncthreads();

        // ================= Phase B: cell-1 state update =================
        {
            int j = i0 >> 4, b = i0 & 15;
            float iv = ag[( 0*HH + j)*AGP + b];
            float fv = ag[( 1*HH + j)*AGP + b];
            float gv = ag[( 2*HH + j)*AGP + b];
            float ov = ag[( 3*HH + j)*AGP + b];
            float c = fv * c1s[0] + iv * gv;
            c1s[0] = c;
            h1[(j << 4) + b] = ov * tanh_c(c);
            if (v1) {
                int j2 = i1 >> 4, b2 = i1 & 15;
                float iw = ag[( 0*HH + j2)*AGP + b2];
                float fw = ag[( 1*HH + j2)*AGP + b2];
                float gw = ag[( 2*HH + j2)*AGP + b2];
                float ow = ag[( 3*HH + j2)*AGP + b2];
                float c2v = fw * c1s[1] + iw * gw;
                c1s[1] = c2v;
                h1[(j2 << 4) + b2] = ow * tanh_c(c2v);
            }
        }
        __syncthreads();

        // ================= Phase C: cell-2 gates (k-half partial) ==========
        if (khalf == 0) {
#pragma unroll
            for (int i = 0; i < 8; ++i) acc[i] = b2d;
        } else {
#pragma unroll
            for (int i = 0; i < 8; ++i) acc[i] = zero;
        }
#pragma unroll
        for (int j = 0; j < KQ; ++j) {
            u64 wd1 = pack2(Wi2r[j], Wi2r[j]);
            u64 wd2 = pack2(Wh2r[j], Wh2r[j]);
            const ulonglong2* h1r = (const ulonglong2*)(h1p + (j << 3));
            const ulonglong2* h2r = (const ulonglong2*)(h2p + (j << 3));
            ulonglong2 p0 = h1r[0], p1 = h1r[1], p2 = h1r[2], p3 = h1r[3];
            ulonglong2 q0 = h2r[0], q1 = h2r[1], q2 = h2r[2], q3 = h2r[3];
            acc[0] = fma2(wd1, p0.x, acc[0]);
            acc[1] = fma2(wd1, p0.y, acc[1]);
            acc[2] = fma2(wd1, p1.x, acc[2]);
            acc[3] = fma2(wd1, p1.y, acc[3]);
            acc[4] = fma2(wd1, p2.x, acc[4]);
            acc[5] = fma2(wd1, p2.y, acc[5]);
            acc[6] = fma2(wd1, p3.x, acc[6]);
            acc[7] = fma2(wd1, p3.y, acc[7]);
            acc[0] = fma2(wd2, q0.x, acc[0]);
            acc[1] = fma2(wd2, q0.y, acc[1]);
            acc[2] = fma2(wd2, q1.x, acc[2]);
            acc[3] = fma2(wd2, q1.y, acc[3]);
            acc[4] = fma2(wd2, q2.x, acc[4]);
            acc[5] = fma2(wd2, q2.y, acc[5]);
            acc[6] = fma2(wd2, q3.x, acc[6]);
            acc[7] = fma2(wd2, q3.y, acc[7]);
        }
        {
            float r[16];
#pragma unroll
            for (int i = 0; i < 8; ++i) unpack2(acc[i], r[2*i], r[2*i+1]);
#pragma unroll
            for (int i = 0; i < 16; ++i)
                r[i] += __shfl_xor_sync(0xFFFFFFFFu, r[i], 16);
            const int off = khalf * 8;
            float s0 = actf(r[off+0], c0, a0, d0);
            float s1 = actf(r[off+1], c0, a0, d0);
            float s2 = actf(r[off+2], c0, a0, d0);
            float s3 = actf(r[off+3], c0, a0, d0);
            float s4 = actf(r[off+4], c0, a0, d0);
            float s5 = actf(r[off+5], c0, a0, d0);
            float s6 = actf(r[off+6], c0, a0, d0);
            float s7 = actf(r[off+7], c0, a0, d0);
            if (valid) {
                *(float4*)&ag[agb]     = make_float4(s0, s1, s2, s3);
                *(float4*)&ag[agb + 4] = make_float4(s4, s5, s6, s7);
            }
        }
        __syncthreads();

        // ================= Phase D: cell-2 state update =================
        {
            int j = i0 >> 4, b = i0 & 15;
            float iv = ag[( 0*HH + j)*AGP + b];
            float fv = ag[( 1*HH + j)*AGP + b];
            float gv = ag[( 2*HH + j)*AGP + b];
            float ov = ag[( 3*HH + j)*AGP + b];
            float c = fv * c2s[0] + iv * gv;
            c2s[0] = c;
            h2[(j << 4) + b] = ov * tanh_c(c);
            if (v1) {
                int j2 = i1 >> 4, b2 = i1 & 15;
                float iw = ag[( 0*HH + j2)*AGP + b2];
                float fw = ag[( 1*HH + j2)*AGP + b2];
                float gw = ag[( 2*HH + j2)*AGP + b2];
                float ow = ag[( 3*HH + j2)*AGP + b2];
                float c2v = fw * c2s[1] + iw * gw;
                c2s[1] = c2v;
                h2[(j2 << 4) + b2] = ow * tanh_c(c2v);
            }
        }
        __syncthreads();

        // ================= Phase E: fc head =================
        if (tid < 64) {
            int b = tid >> 2, q = tid & 3;
            float a = 0.f;
            for (int k = q; k < HH; k += 4)
                a += h2[(k << 4) + b] * sfcw[k];
            a += __shfl_xor_sync(0xFFFFFFFFu, a, 1);
            a += __shfl_xor_sync(0xFFFFFFFFu, a, 2);
            if (q == 0) out[(size_t)(b0 + b) * TT + t] = a + fcb;
        }
        // next h2 writes are in Phase D(t+1), 3 barriers away — safe
    }
}

extern "C" void kernel_launch(void* const* d_in, const int* in_sizes, int n_in,
                              void* d_out, int out_size)
{
    const float* x    = (const float*)d_in[0];
    // d_in[1] = future (0) — ignored
    const float* Wih1 = (const float*)d_in[2];
    const float* bih1 = (const float*)d_in[3];
    const float* Whh1 = (const float*)d_in[4];
    const float* bhh1 = (const float*)d_in[5];
    const float* Wih2 = (const float*)d_in[6];
    const float* bih2 = (const float*)d_in[7];
    const float* Whh2 = (const float*)d_in[8];
    const float* bhh2 = (const float*)d_in[9];
    const float* fcw  = (const float*)d_in[10];
    const float* fcb  = (const float*)d_in[11];
    float* out = (float*)d_out;

    lstm2_ksplit_kernel<<<BB / BT, NTH>>>(
        x, Wih1, bih1, Whh1, bhh1, Wih2, bih2, Whh2, bhh2, fcw, fcb, out);
}

// round 10
// speedup vs baseline: 1.1143x; 1.1143x over previous
#include <cuda_runtime.h>
#include <cstddef>

#define HH 51
#define NT 224       // 7 warps: warp w owns units j = 8w..8w+7, lane = cls*8 + (j&7)
#define BT 16
#define TT 512
#define BB 2048
#define TCH 64

typedef unsigned long long u64;

__device__ __forceinline__ u64 pack2(float lo, float hi) {
    u64 r; asm("mov.b64 %0, {%1,%2};" : "=l"(r) : "f"(lo), "f"(hi)); return r;
}
__device__ __forceinline__ void unpack2(u64 v, float& lo, float& hi) {
    asm("mov.b64 {%0,%1}, %2;" : "=f"(lo), "=f"(hi) : "l"(v));
}
__device__ __forceinline__ u64 fma2(u64 a, u64 b, u64 c) {
    u64 d; asm("fma.rn.f32x2 %0, %1, %2, %3;" : "=l"(d) : "l"(a), "l"(b), "l"(c)); return d;
}
__device__ __forceinline__ float actf(float v, float c, float a, float d) {
    float e; asm("ex2.approx.ftz.f32 %0, %1;" : "=f"(e) : "f"(v * c));
    float r; asm("rcp.approx.ftz.f32 %0, %1;" : "=f"(r) : "f"(1.f + e));
    return fmaf(a, r, d);
}
#define C_SIG (-1.442695041f)
#define C_TNH ( 2.885390082f)
__device__ __forceinline__ float tanh_c(float v) { return actf(v, C_TNH, -2.f, 1.f); }

// Transpose gate x batch inside the warp, update cell state (regs), write h row.
// acc[i] holds pre-activations for batches (2i, 2i+1) of this thread's gate.
__device__ __forceinline__ void gates_update(
    u64 acc[8], float c0, float a0, float d0,
    int bit0, int bit1, float (&cst)[4],
    float* __restrict__ hw, int j, bool jv)
{
    float s[16];
#pragma unroll
    for (int i = 0; i < 8; ++i) unpack2(acc[i], s[2*i], s[2*i+1]);
#pragma unroll
    for (int i = 0; i < 16; ++i) s[i] = actf(s[i], c0, a0, d0);

    // round 1 (xor 8): exchange quarters q with q&1 != bit0; keep q&1 == bit0
    float a1[8];
    {
        const int qx0 = bit0 ? 0 : 1, qx1 = bit0 ? 2 : 3;
        const int qk0 = bit0 ? 1 : 0, qk1 = bit0 ? 3 : 2;
        float ex[8];
#pragma unroll
        for (int i = 0; i < 4; ++i) { ex[i] = s[qx0*4+i]; ex[4+i] = s[qx1*4+i]; }
#pragma unroll
        for (int i = 0; i < 8; ++i) a1[i] = __shfl_xor_sync(0xFFFFFFFFu, ex[i], 8);
        float k0[8];
#pragma unroll
        for (int i = 0; i < 4; ++i) { k0[i] = s[qk0*4+i]; k0[4+i] = s[qk1*4+i]; }
#pragma unroll
        for (int i = 0; i < 8; ++i) s[i] = k0[i];
        // s[0..7]: gate cls, quarters {q&1==bit0} ; a1: gate cls^1, same quarters
    }
    // round 2 (xor 16): keep quarter with q>>1 == bit1, send the other
    float r0[4], r1[4];
    {
        float ex[8];
#pragma unroll
        for (int i = 0; i < 4; ++i) {
            ex[i]   = bit1 ? s[i]    : s[4+i];
            ex[4+i] = bit1 ? a1[i]   : a1[4+i];
        }
#pragma unroll
        for (int i = 0; i < 8; ++i) ex[i] = __shfl_xor_sync(0xFFFFFFFFu, ex[i], 16);
#pragma unroll
        for (int i = 0; i < 4; ++i) {
            r0[i] = ex[i]; r1[i] = ex[4+i];
            s[i]  = bit1 ? s[4+i]  : s[i];    // K0: gate cls,   q = cls
            a1[i] = bit1 ? a1[4+i] : a1[i];   // K1: gate cls^1, q = cls
        }
        // r0: gate cls^2 q=cls ; r1: gate cls^3 q=cls
    }
    // gate_val[cls^0]=K0, [cls^1]=K1, [cls^2]=r0, [cls^3]=r1
    float4 hv;
    float* hp = &hv.x;
#pragma unroll
    for (int i = 0; i < 4; ++i) {
        float iv = bit1 ? (bit0 ? r1[i] : r0[i]) : (bit0 ? a1[i] : s[i]);
        float fv = bit1 ? (bit0 ? r0[i] : r1[i]) : (bit0 ? s[i]  : a1[i]);
        float gv = bit1 ? (bit0 ? a1[i] : s[i])  : (bit0 ? r1[i] : r0[i]);
        float ov = bit1 ? (bit0 ? s[i]  : a1[i]) : (bit0 ? r0[i] : r1[i]);
        float c = fv * cst[i] + iv * gv;
        cst[i] = c;
        hp[i] = ov * tanh_c(c);
    }
    if (jv) *(float4*)&hw[(j << 4) + (bit1*2 + bit0)*4] = hv;  // b = cls*4..+3
}

__global__ void __launch_bounds__(NT, 1) lstm2_fused_kernel(
    const float* __restrict__ x,
    const float* __restrict__ Wih1, const float* __restrict__ bih1,
    const float* __restrict__ Whh1, const float* __restrict__ bhh1,
    const float* __restrict__ Wih2, const float* __restrict__ bih2,
    const float* __restrict__ Whh2, const float* __restrict__ bhh2,
    const float* __restrict__ fcwg, const float* __restrict__ fcbg,
    float* __restrict__ out)
{
    __shared__ __align__(16) float h1d[2][52*BT];   // ping-pong [k][b]
    __shared__ __align__(16) float h2d[2][52*BT];
    __shared__ __align__(16) float xs2[TCH*BT];     // [tc][b]
    __shared__ float sfcw[64];

    const int tid  = threadIdx.x;
    const int b0   = blockIdx.x * BT;
    const int lane = tid & 31, warp = tid >> 5;
    const int cls  = lane >> 3;                      // 0:i 1:f 2:g 3:o
    const int j    = warp * 8 + (lane & 7);          // 0..55 (51..55 pad)
    const bool jv  = (j < HH);
    const int gs   = cls*HH + (jv ? j : HH - 1);
    const int bit0 = cls & 1, bit1 = (cls >> 1) & 1;

    // ---- weights into registers ----
    float W1r[HH], Wi2r[HH], Wh2r[HH];
#pragma unroll
    for (int k = 0; k < HH; ++k) W1r[k]  = Whh1[gs*HH + k];
#pragma unroll
    for (int k = 0; k < HH; ++k) Wi2r[k] = Wih2[gs*HH + k];
#pragma unroll
    for (int k = 0; k < HH; ++k) Wh2r[k] = Whh2[gs*HH + k];

    const float b1 = bih1[gs] + bhh1[gs];
    const float b2 = bih2[gs] + bhh2[gs];
    const float w1x = Wih1[gs];
    const u64 b1d  = pack2(b1, b1);
    const u64 b2d  = pack2(b2, b2);
    const u64 wi1d = pack2(w1x, w1x);

    const float c0 = (cls == 2) ? C_TNH : C_SIG;
    const float a0 = (cls == 2) ? -2.f  : 1.f;
    const float d0 = (cls == 2) ?  1.f  : 0.f;

    for (int i = tid; i < 52*BT; i += NT) {
        h1d[0][i] = 0.f; h1d[1][i] = 0.f;
        h2d[0][i] = 0.f; h2d[1][i] = 0.f;
    }
    if (tid < HH) sfcw[tid] = fcwg[tid];
    const float fcb = fcbg[0];

    float c1s[4] = {0.f, 0.f, 0.f, 0.f};
    float c2s[4] = {0.f, 0.f, 0.f, 0.f};

    __syncthreads();

    for (int t = 0; t < TT; ++t) {
        const int tc = t & (TCH - 1);
        if (tc == 0) {
            __syncthreads();   // prior readers of xs2 / h2 done (bar2 of t-1 also helps)
            for (int i = tid; i < BT*TCH; i += NT) {
                int b = i >> 6, u = i & 63;
                xs2[(u << 4) + b] = x[(size_t)(b0 + b) * TT + t + u];
            }
            __syncthreads();
        }

        const float* h1r = h1d[(t + 1) & 1];   // state from t-1
        float*       h1w = h1d[t & 1];
        const float* h2r = h2d[(t + 1) & 1];
        float*       h2w = h2d[t & 1];

        // ======== cell 1: gates + fused state update ========
        u64 acc[8];
        {
            const ulonglong2* xr = (const ulonglong2*)&xs2[tc << 4];
            ulonglong2 x01 = xr[0], x23 = xr[1], x45 = xr[2], x67 = xr[3];
            acc[0] = fma2(wi1d, x01.x, b1d);
            acc[1] = fma2(wi1d, x01.y, b1d);
            acc[2] = fma2(wi1d, x23.x, b1d);
            acc[3] = fma2(wi1d, x23.y, b1d);
            acc[4] = fma2(wi1d, x45.x, b1d);
            acc[5] = fma2(wi1d, x45.y, b1d);
            acc[6] = fma2(wi1d, x67.x, b1d);
            acc[7] = fma2(wi1d, x67.y, b1d);
        }
#pragma unroll
        for (int k = 0; k < HH; ++k) {
            u64 wd = pack2(W1r[k], W1r[k]);
            const ulonglong2* hr = (const ulonglong2*)&h1r[k << 4];
            ulonglong2 p0 = hr[0], p1 = hr[1], p2 = hr[2], p3 = hr[3];
            acc[0] = fma2(wd, p0.x, acc[0]);
            acc[1] = fma2(wd, p0.y, acc[1]);
            acc[2] = fma2(wd, p1.x, acc[2]);
            acc[3] = fma2(wd, p1.y, acc[3]);
            acc[4] = fma2(wd, p2.x, acc[4]);
            acc[5] = fma2(wd, p2.y, acc[5]);
            acc[6] = fma2(wd, p3.x, acc[6]);
            acc[7] = fma2(wd, p3.y, acc[7]);
        }
        gates_update(acc, c0, a0, d0, bit0, bit1, c1s, h1w, j, jv);
        __syncthreads();                       // h1w visible

        // ======== cell 2: gates + fused state update ========
#pragma unroll
        for (int i = 0; i < 8; ++i) acc[i] = b2d;
#pragma unroll
        for (int k = 0; k < HH; ++k) {
            u64 wd1 = pack2(Wi2r[k], Wi2r[k]);
            u64 wd2 = pack2(Wh2r[k], Wh2r[k]);
            const ulonglong2* h1p = (const ulonglong2*)&h1w[k << 4];
            const ulonglong2* h2p = (const ulonglong2*)&h2r[k << 4];
            ulonglong2 p0 = h1p[0], p1 = h1p[1], p2 = h1p[2], p3 = h1p[3];
            ulonglong2 q0 = h2p[0], q1 = h2p[1], q2 = h2p[2], q3 = h2p[3];
            acc[0] = fma2(wd1, p0.x, acc[0]);
            acc[1] = fma2(wd1, p0.y, acc[1]);
            acc[2] = fma2(wd1, p1.x, acc[2]);
            acc[3] = fma2(wd1, p1.y, acc[3]);
            acc[4] = fma2(wd1, p2.x, acc[4]);
            acc[5] = fma2(wd1, p2.y, acc[5]);
            acc[6] = fma2(wd1, p3.x, acc[6]);
            acc[7] = fma2(wd1, p3.y, acc[7]);
            acc[0] = fma2(wd2, q0.x, acc[0]);
            acc[1] = fma2(wd2, q0.y, acc[1]);
            acc[2] = fma2(wd2, q1.x, acc[2]);
            acc[3] = fma2(wd2, q1.y, acc[3]);
            acc[4] = fma2(wd2, q2.x, acc[4]);
            acc[5] = fma2(wd2, q2.y, acc[5]);
            acc[6] = fma2(wd2, q3.x, acc[6]);
            acc[7] = fma2(wd2, q3.y, acc[7]);
        }
        gates_update(acc, c0, a0, d0, bit0, bit1, c2s, h2w, j, jv);
        __syncthreads();                       // h2w visible

        // ======== fc head (overlaps next step's cell-1 in other warps) ========
        if (tid < 64) {
            int b = tid >> 2, q = tid & 3;
            float a = 0.f;
            for (int k = q; k < HH; k += 4)
                a += h2w[(k << 4) + b] * sfcw[k];
            a += __shfl_xor_sync(0xFFFFFFFFu, a, 1);
            a += __shfl_xor_sync(0xFFFFFFFFu, a, 2);
            if (q == 0) out[(size_t)(b0 + b) * TT + t] = a + fcb;
        }
        // E(t) reads h2w[t&1]; the next write to that buffer is cell-2 of t+2,
        // which is separated by >= 3 barriers. Safe.
    }
}

extern "C" void kernel_launch(void* const* d_in, const int* in_sizes, int n_in,
                              void* d_out, int out_size)
{
    const float* x    = (const float*)d_in[0];
    // d_in[1] = future (0) — ignored
    const float* Wih1 = (const float*)d_in[2];
    const float* bih1 = (const float*)d_in[3];
    const float* Whh1 = (const float*)d_in[4];
    const float* bhh1 = (const float*)d_in[5];
    const float* Wih2 = (const float*)d_in[6];
    const float* bih2 = (const float*)d_in[7];
    const float* Whh2 = (const float*)d_in[8];
    const float* bhh2 = (const float*)d_in[9];
    const float* fcw  = (const float*)d_in[10];
    const float* fcb  = (const float*)d_in[11];
    float* out = (float*)d_out;

    lstm2_fused_kernel<<<BB / BT, NT>>>(
        x, Wih1, bih1, Whh1, bhh1, Wih2, bih2, Whh2, bhh2, fcw, fcb, out);
}

// round 14
// speedup vs baseline: 1.4333x; 1.2862x over previous
#include <cuda_runtime.h>
#include <cstddef>

#define HH 51
#define NT 224       // 7 warps: warp w owns units j = 8w..8w+7, lane = cls*8 + (j&7)
#define BT 16
#define TT 512
#define BB 2048
#define TCH 64

typedef unsigned long long u64;

__device__ __forceinline__ u64 pack2(float lo, float hi) {
    u64 r; asm("mov.b64 %0, {%1,%2};" : "=l"(r) : "f"(lo), "f"(hi)); return r;
}
__device__ __forceinline__ void unpack2(u64 v, float& lo, float& hi) {
    asm("mov.b64 {%0,%1}, %2;" : "=f"(lo), "=f"(hi) : "l"(v));
}
__device__ __forceinline__ u64 fma2(u64 a, u64 b, u64 c) {
    u64 d; asm("fma.rn.f32x2 %0, %1, %2, %3;" : "=l"(d) : "l"(a), "l"(b), "l"(c)); return d;
}
// v is PRE-SCALED by the log2 constant (weights folded). act = a*rcp(1+ex2(v)) + d
__device__ __forceinline__ float actf2(float v, float a, float d) {
    float e; asm("ex2.approx.ftz.f32 %0, %1;" : "=f"(e) : "f"(v));
    float r; asm("rcp.approx.ftz.f32 %0, %1;" : "=f"(r) : "f"(1.f + e));
    return fmaf(a, r, d);
}
#define C_SIG (-1.442695041f)
#define C_TNH ( 2.885390082f)
__device__ __forceinline__ float tanh_c(float v) {   // plain tanh (for cell state)
    float e; asm("ex2.approx.ftz.f32 %0, %1;" : "=f"(e) : "f"(v * C_TNH));
    float r; asm("rcp.approx.ftz.f32 %0, %1;" : "=f"(r) : "f"(1.f + e));
    return fmaf(-2.f, r, 1.f);
}

// Transpose gate x batch inside the warp, update cell state (regs), write h row.
// acc[i] holds PRE-SCALED pre-activations for batches (2i, 2i+1) of this thread's gate.
__device__ __forceinline__ void gates_update(
    u64 acc[8], float a0, float d0,
    int bit0, int bit1, float (&cst)[4],
    float* __restrict__ hw, int j, bool jv)
{
    float s[16];
#pragma unroll
    for (int i = 0; i < 8; ++i) unpack2(acc[i], s[2*i], s[2*i+1]);
#pragma unroll
    for (int i = 0; i < 16; ++i) s[i] = actf2(s[i], a0, d0);

    // round 1 (xor 8): exchange quarters q with q&1 != bit0; keep q&1 == bit0
    float a1[8];
    {
        const int qx0 = bit0 ? 0 : 1, qx1 = bit0 ? 2 : 3;
        const int qk0 = bit0 ? 1 : 0, qk1 = bit0 ? 3 : 2;
        float ex[8];
#pragma unroll
        for (int i = 0; i < 4; ++i) { ex[i] = s[qx0*4+i]; ex[4+i] = s[qx1*4+i]; }
#pragma unroll
        for (int i = 0; i < 8; ++i) a1[i] = __shfl_xor_sync(0xFFFFFFFFu, ex[i], 8);
        float k0[8];
#pragma unroll
        for (int i = 0; i < 4; ++i) { k0[i] = s[qk0*4+i]; k0[4+i] = s[qk1*4+i]; }
#pragma unroll
        for (int i = 0; i < 8; ++i) s[i] = k0[i];
    }
    // round 2 (xor 16): keep quarter with q>>1 == bit1, send the other
    float r0[4], r1[4];
    {
        float ex[8];
#pragma unroll
        for (int i = 0; i < 4; ++i) {
            ex[i]   = bit1 ? s[i]  : s[4+i];
            ex[4+i] = bit1 ? a1[i] : a1[4+i];
        }
#pragma unroll
        for (int i = 0; i < 8; ++i) ex[i] = __shfl_xor_sync(0xFFFFFFFFu, ex[i], 16);
#pragma unroll
        for (int i = 0; i < 4; ++i) {
            r0[i] = ex[i]; r1[i] = ex[4+i];
            s[i]  = bit1 ? s[4+i]  : s[i];
            a1[i] = bit1 ? a1[4+i] : a1[i];
        }
    }
    float4 hv;
    float* hp = &hv.x;
#pragma unroll
    for (int i = 0; i < 4; ++i) {
        float iv = bit1 ? (bit0 ? r1[i] : r0[i]) : (bit0 ? a1[i] : s[i]);
        float fv = bit1 ? (bit0 ? r0[i] : r1[i]) : (bit0 ? s[i]  : a1[i]);
        float gv = bit1 ? (bit0 ? a1[i] : s[i])  : (bit0 ? r1[i] : r0[i]);
        float ov = bit1 ? (bit0 ? s[i]  : a1[i]) : (bit0 ? r0[i] : r1[i]);
        float c = fv * cst[i] + iv * gv;
        cst[i] = c;
        hp[i] = ov * tanh_c(c);
    }
    if (jv) *(float4*)&hw[(j << 4) + (bit1*2 + bit0)*4] = hv;
}

__global__ void __launch_bounds__(NT, 1) lstm2_onebar_kernel(
    const float* __restrict__ x,
    const float* __restrict__ Wih1, const float* __restrict__ bih1,
    const float* __restrict__ Whh1, const float* __restrict__ bhh1,
    const float* __restrict__ Wih2, const float* __restrict__ bih2,
    const float* __restrict__ Whh2, const float* __restrict__ bhh2,
    const float* __restrict__ fcwg, const float* __restrict__ fcbg,
    float* __restrict__ out)
{
    __shared__ __align__(16) float h1d[2][52*BT];   // ping-pong [k][b]
    __shared__ __align__(16) float h2d[2][52*BT];
    __shared__ __align__(16) float xs2[TCH*BT];     // [tc][b]
    __shared__ float sfcw[64];

    const int tid  = threadIdx.x;
    const int b0   = blockIdx.x * BT;
    const int lane = tid & 31, warp = tid >> 5;
    const int cls  = lane >> 3;                      // 0:i 1:f 2:g 3:o
    const int j    = warp * 8 + (lane & 7);          // 0..55 (51..55 pad)
    const bool jv  = (j < HH);
    const int gs   = cls*HH + (jv ? j : HH - 1);
    const int bit0 = cls & 1, bit1 = (cls >> 1) & 1;

    // activation constants; weights PRE-SCALED by sc
    const float sc = (cls == 2) ? C_TNH : C_SIG;
    const float a0 = (cls == 2) ? -2.f  : 1.f;
    const float d0 = (cls == 2) ?  1.f  : 0.f;

    // ---- weights into registers (pre-scaled) ----
    float W1r[HH], Wi2r[HH], Wh2r[HH];
#pragma unroll
    for (int k = 0; k < HH; ++k) W1r[k]  = sc * Whh1[gs*HH + k];
#pragma unroll
    for (int k = 0; k < HH; ++k) Wi2r[k] = sc * Wih2[gs*HH + k];
#pragma unroll
    for (int k = 0; k < HH; ++k) Wh2r[k] = sc * Whh2[gs*HH + k];

    const float b1 = sc * (bih1[gs] + bhh1[gs]);
    const float b2 = sc * (bih2[gs] + bhh2[gs]);
    const float w1x = sc * Wih1[gs];
    const u64 b1d  = pack2(b1, b1);
    const u64 b2d  = pack2(b2, b2);
    const u64 wi1d = pack2(w1x, w1x);

    for (int i = tid; i < 52*BT; i += NT) {
        h1d[0][i] = 0.f; h1d[1][i] = 0.f;
        h2d[0][i] = 0.f; h2d[1][i] = 0.f;
    }
    if (tid < HH) sfcw[tid] = fcwg[tid];
    const float fcb = fcbg[0];

    float c1s[4] = {0.f, 0.f, 0.f, 0.f};
    float c2s[4] = {0.f, 0.f, 0.f, 0.f};

    // stage x chunk 0
    for (int i = tid; i < BT*TCH; i += NT) {
        int b = i >> 6, u = i & 63;
        xs2[(u << 4) + b] = x[(size_t)(b0 + b) * TT + u];
    }
    __syncthreads();

    // ---- prologue: cell1 at t=0 (h1(-1)=0 -> gates are x-term + bias only) ----
    {
        u64 a1c[8];
        const ulonglong2* xr = (const ulonglong2*)&xs2[0];
        ulonglong2 x01 = xr[0], x23 = xr[1], x45 = xr[2], x67 = xr[3];
        a1c[0] = fma2(wi1d, x01.x, b1d);
        a1c[1] = fma2(wi1d, x01.y, b1d);
        a1c[2] = fma2(wi1d, x23.x, b1d);
        a1c[3] = fma2(wi1d, x23.y, b1d);
        a1c[4] = fma2(wi1d, x45.x, b1d);
        a1c[5] = fma2(wi1d, x45.y, b1d);
        a1c[6] = fma2(wi1d, x67.x, b1d);
        a1c[7] = fma2(wi1d, x67.y, b1d);
        gates_update(a1c, a0, d0, bit0, bit1, c1s, h1d[0], j, jv);
    }
    __syncthreads();

    // ================= main loop: ONE barrier per timestep =================
    // entry invariant: h1(t) in h1d[t&1], h2(t-1) in h2d[(t+1)&1]
    for (int t = 0; t < TT; ++t) {
        // ---- fc head for step t-1 (reads h2d[(t-1)&1], stable this whole iter) ----
        if (t > 0 && tid < 128) {
            const float* h2p = h2d[(t - 1) & 1];
            int b = tid >> 3, q = tid & 7;
            float a = 0.f;
            for (int k = q; k < HH; k += 8)
                a += h2p[(k << 4) + b] * sfcw[k];
            a += __shfl_xor_sync(0xFFFFFFFFu, a, 1);
            a += __shfl_xor_sync(0xFFFFFFFFu, a, 2);
            a += __shfl_xor_sync(0xFFFFFFFFu, a, 4);
            if (q == 0) out[(size_t)(b0 + b) * TT + (t - 1)] = a + fcb;
        }

        // ---- restage x when crossing a 64-step chunk (needs x(t+1)) ----
        const int tn = t + 1;
        if ((tn & 63) == 0 && t < TT - 1) {
            __syncthreads();   // prior xs2 readers done (entry barrier covers t-1's reads; this covers t's? none yet this iter)
            for (int i = tid; i < BT*TCH; i += NT) {
                int b = i >> 6, u = i & 63;
                xs2[(u << 4) + b] = x[(size_t)(b0 + b) * TT + tn + u];
            }
            __syncthreads();
        }
        const int tc = tn & 63;   // at t=511 this indexes stale data; result discarded

        const float* h1cur = h1d[t & 1];
        const float* h2prv = h2d[(t + 1) & 1];
        float*       h1nxt = h1d[(t + 1) & 1];
        float*       h2cur = h2d[t & 1];

        // ---- unified gate phase: gates1(t+1) and gates2(t) share h1(t) loads ----
        u64 a1c[8], a2c[8];
        {
            const ulonglong2* xr = (const ulonglong2*)&xs2[tc << 4];
            ulonglong2 x01 = xr[0], x23 = xr[1], x45 = xr[2], x67 = xr[3];
            a1c[0] = fma2(wi1d, x01.x, b1d);
            a1c[1] = fma2(wi1d, x01.y, b1d);
            a1c[2] = fma2(wi1d, x23.x, b1d);
            a1c[3] = fma2(wi1d, x23.y, b1d);
            a1c[4] = fma2(wi1d, x45.x, b1d);
            a1c[5] = fma2(wi1d, x45.y, b1d);
            a1c[6] = fma2(wi1d, x67.x, b1d);
            a1c[7] = fma2(wi1d, x67.y, b1d);
        }
#pragma unroll
        for (int i = 0; i < 8; ++i) a2c[i] = b2d;

#pragma unroll
        for (int k = 0; k < HH; ++k) {
            u64 w1 = pack2(W1r[k],  W1r[k]);
            u64 wi = pack2(Wi2r[k], Wi2r[k]);
            u64 wh = pack2(Wh2r[k], Wh2r[k]);
            const ulonglong2* hp = (const ulonglong2*)&h1cur[k << 4];
            const ulonglong2* hq = (const ulonglong2*)&h2prv[k << 4];
            ulonglong2 p0 = hp[0], p1 = hp[1], p2 = hp[2], p3 = hp[3];
            ulonglong2 q0 = hq[0], q1 = hq[1], q2 = hq[2], q3 = hq[3];
            // cell-1 next gates (Whh1 @ h1)
            a1c[0] = fma2(w1, p0.x, a1c[0]);
            a1c[1] = fma2(w1, p0.y, a1c[1]);
            a1c[2] = fma2(w1, p1.x, a1c[2]);
            a1c[3] = fma2(w1, p1.y, a1c[3]);
            a1c[4] = fma2(w1, p2.x, a1c[4]);
            a1c[5] = fma2(w1, p2.y, a1c[5]);
            a1c[6] = fma2(w1, p3.x, a1c[6]);
            a1c[7] = fma2(w1, p3.y, a1c[7]);
            // cell-2 gates, input term (Wih2 @ h1)
            a2c[0] = fma2(wi, p0.x, a2c[0]);
            a2c[1] = fma2(wi, p0.y, a2c[1]);
            a2c[2] = fma2(wi, p1.x, a2c[2]);
            a2c[3] = fma2(wi, p1.y, a2c[3]);
            a2c[4] = fma2(wi, p2.x, a2c[4]);
            a2c[5] = fma2(wi, p2.y, a2c[5]);
            a2c[6] = fma2(wi, p3.x, a2c[6]);
            a2c[7] = fma2(wi, p3.y, a2c[7]);
            // cell-2 gates, recurrent term (Whh2 @ h2)
            a2c[0] = fma2(wh, q0.x, a2c[0]);
            a2c[1] = fma2(wh, q0.y, a2c[1]);
            a2c[2] = fma2(wh, q1.x, a2c[2]);
            a2c[3] = fma2(wh, q1.y, a2c[3]);
            a2c[4] = fma2(wh, q2.x, a2c[4]);
            a2c[5] = fma2(wh, q2.y, a2c[5]);
            a2c[6] = fma2(wh, q3.x, a2c[6]);
            a2c[7] = fma2(wh, q3.y, a2c[7]);
        }

        // ---- updates: h2(t) then h1(t+1); both into write buffers ----
        gates_update(a2c, a0, d0, bit0, bit1, c2s, h2cur, j, jv);
        gates_update(a1c, a0, d0, bit0, bit1, c1s, h1nxt, j, jv);

        __syncthreads();   // h1(t+1), h2(t) visible; xs2/h reads of this iter done
    }

    // ---- final fc for t = 511 ----
    if (tid < 128) {
        const float* h2p = h2d[(TT - 1) & 1];
        int b = tid >> 3, q = tid & 7;
        float a = 0.f;
        for (int k = q; k < HH; k += 8)
            a += h2p[(k << 4) + b] * sfcw[k];
        a += __shfl_xor_sync(0xFFFFFFFFu, a, 1);
        a += __shfl_xor_sync(0xFFFFFFFFu, a, 2);
        a += __shfl_xor_sync(0xFFFFFFFFu, a, 4);
        if (q == 0) out[(size_t)(b0 + b) * TT + (TT - 1)] = a + fcb;
    }
}

extern "C" void kernel_launch(void* const* d_in, const int* in_sizes, int n_in,
                              void* d_out, int out_size)
{
    const float* x    = (const float*)d_in[0];
    // d_in[1] = future (0) — ignored
    const float* Wih1 = (const float*)d_in[2];
    const float* bih1 = (const float*)d_in[3];
    const float* Whh1 = (const float*)d_in[4];
    const float* bhh1 = (const float*)d_in[5];
    const float* Wih2 = (const float*)d_in[6];
    const float* bih2 = (const float*)d_in[7];
    const float* Whh2 = (const float*)d_in[8];
    const float* bhh2 = (const float*)d_in[9];
    const float* fcw  = (const float*)d_in[10];
    const float* fcb  = (const float*)d_in[11];
    float* out = (float*)d_out;

    lstm2_onebar_kernel<<<BB / BT, NT>>>(
        x, Wih1, bih1, Whh1, bhh1, Wih2, bih2, Whh2, bhh2, fcw, fcb, out);
}